// round 3
// baseline (speedup 1.0000x reference)
#include <cuda_runtime.h>
#include <cuda_bf16.h>

// Problem constants
#define SEQ   4096
#define EMB   128
#define HID   128
#define G4    512          // 4*HID gate rows
#define NT    16

// Scratch (device globals; no allocation allowed)
__device__ int   g_tok[SEQ];
__device__ float g_pre[(SEQ + 1) * G4];   // +1 row so prefetch never branches
__device__ float g_hs[SEQ * HID];

// ---------------------------------------------------------------------------
// fast activations: ex2.approx + rcp.approx (rel err ~1e-7, well under 1e-3)
// ---------------------------------------------------------------------------
__device__ __forceinline__ float f_ex2(float x) {
    float y; asm("ex2.approx.f32 %0, %1;" : "=f"(y) : "f"(x)); return y;
}
__device__ __forceinline__ float f_rcp(float x) {
    float y; asm("rcp.approx.f32 %0, %1;" : "=f"(y) : "f"(x)); return y;
}
__device__ __forceinline__ float f_sigmoid(float x) {
    // 1 / (1 + exp(-x)) = 1 / (1 + 2^(-x*log2e))
    return f_rcp(1.0f + f_ex2(-1.4426950408889634f * x));
}
__device__ __forceinline__ float f_tanh(float x) {
    return 2.0f * f_sigmoid(2.0f * x) - 1.0f;
}

// ---------------------------------------------------------------------------
// Kernel 0: normalize tokens to int32 regardless of whether the harness
// delivered int32 (expected per harness dtype set) or genuine int64.
// Detection: if the buffer is int64, the odd 32-bit words of the first 64
// entries are all zero (tokens in [0, 200000)). For int32 data those words
// are random tokens; P(all 64 == 0) is negligible. Uniform branch, no OOB.
// ---------------------------------------------------------------------------
__global__ void tokenize_kernel(const int* __restrict__ xi) {
    __shared__ int is64;
    if (threadIdx.x == 0) {
        int nz = 0;
        #pragma unroll
        for (int i = 0; i < 64; ++i) nz += (xi[2 * i + 1] != 0);
        is64 = (nz == 0);
    }
    __syncthreads();
    int t = blockIdx.x * blockDim.x + threadIdx.x;
    if (t < SEQ) {
        if (is64) g_tok[t] = xi[2 * t];      // low word of int64
        else      g_tok[t] = xi[t];
    }
}

// ---------------------------------------------------------------------------
// Kernel 1: pre[t][r] = b_ih[r] + b_hh[r] + sum_k emb[tok[t]][k] * w_ih[r][k]
// 256 blocks x 256 threads, 16 timesteps per block, 2 rows per thread.
// ---------------------------------------------------------------------------
__global__ void precompute_kernel(const float* __restrict__ emb,
                                  const float* __restrict__ w_ih,
                                  const float* __restrict__ b_ih,
                                  const float* __restrict__ b_hh,
                                  float* __restrict__ pre) {
    __shared__ float xe[16][128];
    const int t0 = blockIdx.x * 16;

    for (int i = threadIdx.x; i < 16 * 128; i += 256) {
        int ts = i >> 7, k = i & 127;
        long long tok = g_tok[t0 + ts];
        xe[ts][k] = emb[tok * (long long)EMB + k];
    }
    __syncthreads();

    #pragma unroll
    for (int rr = 0; rr < 2; ++rr) {
        const int r = threadIdx.x + rr * 256;
        const float bias = b_ih[r] + b_hh[r];
        float acc[16];
        #pragma unroll
        for (int ts = 0; ts < 16; ++ts) acc[ts] = bias;

        const float4* wrow = reinterpret_cast<const float4*>(w_ih + r * EMB);
        #pragma unroll 8
        for (int k4 = 0; k4 < EMB / 4; ++k4) {
            float4 w = wrow[k4];
            #pragma unroll
            for (int ts = 0; ts < 16; ++ts) {
                float4 h = reinterpret_cast<const float4*>(xe[ts])[k4];
                acc[ts] += w.x * h.x + w.y * h.y + w.z * h.z + w.w * h.w;
            }
        }
        #pragma unroll
        for (int ts = 0; ts < 16; ++ts)
            pre[(t0 + ts) * G4 + r] = acc[ts];
    }
}

// ---------------------------------------------------------------------------
// Kernel 2: the recurrence. Single block, 512 threads, thread t owns gate row t.
// Weights: w_hh[t][0:64]  in registers (16 float4/thread)
//          w_hh[t][64:128] in smem, row stride 68 floats (bank-conflict-free)
// h lives in smem (broadcast reads). c lives in registers of threads 0..127.
// ---------------------------------------------------------------------------
#define WS_STRIDE 68      // 64 + 4 pad; float4 reads conflict-free

__global__ void __launch_bounds__(512, 1)
lstm_kernel(const float* __restrict__ w_hh,
            const float* __restrict__ pre,
            float* __restrict__ hs) {
    extern __shared__ float smem[];
    float* ws   = smem;                         // 512 * 68 floats
    float* h_s  = ws + G4 * WS_STRIDE;          // 128 floats
    float* zact = h_s + HID;                    // 512 floats

    const int t = threadIdx.x;

    // --- load register half of weights: w_hh[t][0:64] ---
    float4 wr[16];
    {
        const float4* wrow = reinterpret_cast<const float4*>(w_hh + t * HID);
        #pragma unroll
        for (int i = 0; i < 16; ++i) wr[i] = wrow[i];
    }
    // --- load smem half: ws[r][k] = w_hh[r][64+k] ---
    for (int idx = t; idx < G4 * 64; idx += 512) {
        int r = idx >> 6, k = idx & 63;
        ws[r * WS_STRIDE + k] = w_hh[r * HID + 64 + k];
    }
    // --- init h = 0 ---
    if (t < HID) h_s[t] = 0.0f;
    float c = 0.0f;

    const float4* h4     = reinterpret_cast<const float4*>(h_s);
    const float4* wsrow  = reinterpret_cast<const float4*>(ws + t * WS_STRIDE);
    const bool is_tanh_gate = (t >= 256) && (t < 384);

    float pre_cur = pre[t];
    __syncthreads();

    for (int s = 0; s < SEQ; ++s) {
        float acc = pre_cur;
        pre_cur = pre[(s + 1) * G4 + t];        // prefetch (row SEQ exists, unused)

        float a0 = 0.f, a1 = 0.f, a2 = 0.f, a3 = 0.f;
        #pragma unroll
        for (int i = 0; i < 16; ++i) {          // register-resident half
            float4 h = h4[i];
            float4 w = wr[i];
            a0 += w.x * h.x; a1 += w.y * h.y; a2 += w.z * h.z; a3 += w.w * h.w;
        }
        #pragma unroll
        for (int i = 0; i < 16; ++i) {          // smem half
            float4 h = h4[16 + i];
            float4 w = wsrow[i];
            a0 += w.x * h.x; a1 += w.y * h.y; a2 += w.z * h.z; a3 += w.w * h.w;
        }
        acc += (a0 + a1) + (a2 + a3);

        // activation: rows [256,384) are g-gate (tanh), rest sigmoid
        float a = is_tanh_gate ? f_tanh(acc) : f_sigmoid(acc);
        zact[t] = a;
        __syncthreads();

        if (t < HID) {
            float ig = zact[t];
            float fg = zact[t + 128];
            float gg = zact[t + 256];
            float og = zact[t + 384];
            c = fg * c + ig * gg;
            float hv = og * f_tanh(c);
            h_s[t] = hv;
            hs[s * HID + t] = hv;
        }
        __syncthreads();
    }
}

// ---------------------------------------------------------------------------
// Kernel 3: out[t][n] = b_fc[n] + sum_k hs[t][k] * w_fc[n][k]
// 256 blocks x 256 threads, 16 timesteps per block.
// ---------------------------------------------------------------------------
__global__ void fc_kernel(const float* __restrict__ hs,
                          const float* __restrict__ w_fc,
                          const float* __restrict__ b_fc,
                          float* __restrict__ out) {
    __shared__ float sh[16][132];
    __shared__ float sw[16][132];
    const int t0 = blockIdx.x * 16;

    for (int i = threadIdx.x; i < 16 * 128; i += 256) {
        int r = i >> 7, k = i & 127;
        sh[r][k] = hs[(t0 + r) * HID + k];
        sw[r][k] = w_fc[r * HID + k];
    }
    __syncthreads();

    const int ts = threadIdx.x >> 4;   // 0..15
    const int n  = threadIdx.x & 15;   // 0..15
    float acc = b_fc[n];
    #pragma unroll 8
    for (int k = 0; k < 128; ++k)
        acc += sh[ts][k] * sw[n][k];
    out[(t0 + ts) * NT + n] = acc;
}

// ---------------------------------------------------------------------------
extern "C" void kernel_launch(void* const* d_in, const int* in_sizes, int n_in,
                              void* d_out, int out_size) {
    const int*   x    = (const int*)d_in[0];
    const float* emb  = (const float*)d_in[1];
    const float* w_ih = (const float*)d_in[2];
    const float* w_hh = (const float*)d_in[3];
    const float* b_ih = (const float*)d_in[4];
    const float* b_hh = (const float*)d_in[5];
    const float* w_fc = (const float*)d_in[6];
    const float* b_fc = (const float*)d_in[7];
    float* out = (float*)d_out;

    float* pre; cudaGetSymbolAddress((void**)&pre, g_pre);
    float* hs;  cudaGetSymbolAddress((void**)&hs,  g_hs);

    const int lstm_smem = (G4 * WS_STRIDE + HID + G4) * (int)sizeof(float);
    cudaFuncSetAttribute(lstm_kernel,
                         cudaFuncAttributeMaxDynamicSharedMemorySize, lstm_smem);

    tokenize_kernel<<<SEQ / 256, 256>>>(x);
    precompute_kernel<<<SEQ / 16, 256>>>(emb, w_ih, b_ih, b_hh, pre);
    lstm_kernel<<<1, 512, lstm_smem>>>(w_hh, pre, hs);
    fc_kernel<<<SEQ / 16, 256>>>(hs, w_fc, b_fc, out);
}

// round 4
// speedup vs baseline: 1.2374x; 1.2374x over previous
#include <cuda_runtime.h>
#include <cuda_bf16.h>

// Problem constants
#define SEQ   4096
#define EMB   128
#define HID   128
#define G4    512          // 4*HID gate rows
#define NT    16

// Scratch (device globals; no allocation allowed)
__device__ int   g_tok[SEQ];
__device__ float g_pre[(SEQ + 1) * G4];   // +1 row so prefetch never branches
__device__ float g_hs[SEQ * HID];

typedef unsigned long long ull;

// ---------------------------------------------------------------------------
// fast math helpers
// ---------------------------------------------------------------------------
__device__ __forceinline__ float f_ex2(float x) {
    float y; asm("ex2.approx.f32 %0, %1;" : "=f"(y) : "f"(x)); return y;
}
__device__ __forceinline__ float f_rcp(float x) {
    float y; asm("rcp.approx.f32 %0, %1;" : "=f"(y) : "f"(x)); return y;
}
__device__ __forceinline__ float f_sigmoid(float x) {
    return f_rcp(1.0f + f_ex2(-1.4426950408889634f * x));
}
__device__ __forceinline__ float f_tanh(float x) {
    return 2.0f * f_sigmoid(2.0f * x) - 1.0f;
}

// packed f32x2 FMA (sm_100+): d.lo = a.lo*b.lo + c.lo ; d.hi likewise
__device__ __forceinline__ ull ffma2(ull a, ull b, ull c) {
    ull d; asm("fma.rn.f32x2 %0, %1, %2, %3;" : "=l"(d) : "l"(a), "l"(b), "l"(c));
    return d;
}
__device__ __forceinline__ ull packf2(float lo, float hi) {
    ull r; asm("mov.b64 %0, {%1, %2};" : "=l"(r) : "f"(lo), "f"(hi)); return r;
}
__device__ __forceinline__ void unpackf2(float& lo, float& hi, ull v) {
    asm("mov.b64 {%0, %1}, %2;" : "=f"(lo), "=f"(hi) : "l"(v));
}
// one LDS.128 delivering two ready-to-use f32x2 operands
__device__ __forceinline__ void lds_v2b64(ull& a, ull& b, unsigned saddr) {
    asm volatile("ld.shared.v2.b64 {%0, %1}, [%2];" : "=l"(a), "=l"(b) : "r"(saddr));
}

// ---------------------------------------------------------------------------
// Kernel 0: normalize tokens to int32 (harness delivers int64 as 2x int32,
// or int32 directly). Odd words of genuine int64 tokens (< 2^31) are zero.
// ---------------------------------------------------------------------------
__global__ void tokenize_kernel(const int* __restrict__ xi) {
    __shared__ int is64;
    if (threadIdx.x == 0) {
        int nz = 0;
        #pragma unroll
        for (int i = 0; i < 64; ++i) nz += (xi[2 * i + 1] != 0);
        is64 = (nz == 0);
    }
    __syncthreads();
    int t = blockIdx.x * blockDim.x + threadIdx.x;
    if (t < SEQ) {
        if (is64) g_tok[t] = xi[2 * t];
        else      g_tok[t] = xi[t];
    }
}

// ---------------------------------------------------------------------------
// Kernel 1: pre[t][r] = b_ih[r] + b_hh[r] + sum_k emb[tok[t]][k] * w_ih[r][k]
// ---------------------------------------------------------------------------
__global__ void precompute_kernel(const float* __restrict__ emb,
                                  const float* __restrict__ w_ih,
                                  const float* __restrict__ b_ih,
                                  const float* __restrict__ b_hh,
                                  float* __restrict__ pre) {
    __shared__ float xe[16][128];
    const int t0 = blockIdx.x * 16;

    for (int i = threadIdx.x; i < 16 * 128; i += 256) {
        int ts = i >> 7, k = i & 127;
        long long tok = g_tok[t0 + ts];
        xe[ts][k] = emb[tok * (long long)EMB + k];
    }
    __syncthreads();

    #pragma unroll
    for (int rr = 0; rr < 2; ++rr) {
        const int r = threadIdx.x + rr * 256;
        const float bias = b_ih[r] + b_hh[r];
        float acc[16];
        #pragma unroll
        for (int ts = 0; ts < 16; ++ts) acc[ts] = bias;

        const float4* wrow = reinterpret_cast<const float4*>(w_ih + r * EMB);
        #pragma unroll 8
        for (int k4 = 0; k4 < EMB / 4; ++k4) {
            float4 w = wrow[k4];
            #pragma unroll
            for (int ts = 0; ts < 16; ++ts) {
                float4 h = reinterpret_cast<const float4*>(xe[ts])[k4];
                acc[ts] += w.x * h.x + w.y * h.y + w.z * h.z + w.w * h.w;
            }
        }
        #pragma unroll
        for (int ts = 0; ts < 16; ++ts)
            pre[(t0 + ts) * G4 + r] = acc[ts];
    }
}

// ---------------------------------------------------------------------------
// Kernel 2: recurrence. 1 block x 512 threads; thread t owns gate row t.
//   w_hh[t][0:96]   -> 48 packed f32x2 register pairs (96 regs)
//   w_hh[t][96:128] -> smem, row stride 36 floats (quarter-warp conflict-free)
//   math: fma.rn.f32x2 (2 MACs/instr, zero per-step packing)
// ---------------------------------------------------------------------------
#define NREG   96                 // weights in registers per row
#define NSH    (HID - NREG)       // 32 weights in smem per row
#define WS_STRIDE 36              // 32 + 4 pad; 36 mod 32 == 4 -> conflict-free

__global__ void __launch_bounds__(512, 1)
lstm_kernel(const float* __restrict__ w_hh,
            const float* __restrict__ pre,
            float* __restrict__ hs) {
    extern __shared__ float smem[];
    float* ws   = smem;                          // 512 * 36 floats
    float* h_s  = ws + G4 * WS_STRIDE;           // 128 floats (16B aligned)
    float* zact = h_s + HID;                     // 512 floats

    const int t = threadIdx.x;

    // --- pack register weights: w_hh[t][0:96] -> 48 b64 pairs ---
    ull wreg[NREG / 2];
    {
        const float4* wrow = reinterpret_cast<const float4*>(w_hh + t * HID);
        #pragma unroll
        for (int i = 0; i < NREG / 4; ++i) {
            float4 w = wrow[i];
            wreg[2 * i]     = packf2(w.x, w.y);
            wreg[2 * i + 1] = packf2(w.z, w.w);
        }
    }
    // --- smem tail: ws[r][k] = w_hh[r][96+k] ---
    for (int idx = t; idx < G4 * NSH; idx += 512) {
        int r = idx >> 5, k = idx & (NSH - 1);
        ws[r * WS_STRIDE + k] = w_hh[r * HID + NREG + k];
    }
    if (t < HID) h_s[t] = 0.0f;
    float c = 0.0f;

    const unsigned h_saddr  = (unsigned)__cvta_generic_to_shared(h_s);
    const unsigned ws_saddr = (unsigned)__cvta_generic_to_shared(ws + t * WS_STRIDE);
    const bool is_tanh_gate = (t >= 256) && (t < 384);

    float pre_cur = pre[t];
    __syncthreads();

    for (int s = 0; s < SEQ; ++s) {
        ull acc0 = packf2(pre_cur, 0.0f);
        ull acc1 = 0;
        pre_cur = pre[(s + 1) * G4 + t];     // prefetch (row SEQ exists, unused)

        #pragma unroll
        for (int i = 0; i < NREG / 4; ++i) {         // register weight half
            ull hp0, hp1;
            lds_v2b64(hp0, hp1, h_saddr + 16u * i);
            acc0 = ffma2(wreg[2 * i],     hp0, acc0);
            acc1 = ffma2(wreg[2 * i + 1], hp1, acc1);
        }
        #pragma unroll
        for (int i = 0; i < NSH / 4; ++i) {          // smem weight tail
            ull hp0, hp1, wp0, wp1;
            lds_v2b64(hp0, hp1, h_saddr + 16u * (NREG / 4 + i));
            lds_v2b64(wp0, wp1, ws_saddr + 16u * i);
            acc0 = ffma2(wp0, hp0, acc0);
            acc1 = ffma2(wp1, hp1, acc1);
        }

        float s0, s1, s2, s3;
        unpackf2(s0, s1, acc0);
        unpackf2(s2, s3, acc1);
        float acc = (s0 + s1) + (s2 + s3);

        float a = is_tanh_gate ? f_tanh(acc) : f_sigmoid(acc);
        zact[t] = a;
        __syncthreads();

        if (t < HID) {
            float ig = zact[t];
            float fg = zact[t + 128];
            float gg = zact[t + 256];
            float og = zact[t + 384];
            c = fg * c + ig * gg;
            float hv = og * f_tanh(c);
            h_s[t] = hv;
            hs[s * HID + t] = hv;
        }
        __syncthreads();
    }
}

// ---------------------------------------------------------------------------
// Kernel 3: out[t][n] = b_fc[n] + sum_k hs[t][k] * w_fc[n][k]
// ---------------------------------------------------------------------------
__global__ void fc_kernel(const float* __restrict__ hs,
                          const float* __restrict__ w_fc,
                          const float* __restrict__ b_fc,
                          float* __restrict__ out) {
    __shared__ float sh[16][132];
    __shared__ float sw[16][132];
    const int t0 = blockIdx.x * 16;

    for (int i = threadIdx.x; i < 16 * 128; i += 256) {
        int r = i >> 7, k = i & 127;
        sh[r][k] = hs[(t0 + r) * HID + k];
        sw[r][k] = w_fc[r * HID + k];
    }
    __syncthreads();

    const int ts = threadIdx.x >> 4;
    const int n  = threadIdx.x & 15;
    float acc = b_fc[n];
    #pragma unroll 8
    for (int k = 0; k < 128; ++k)
        acc += sh[ts][k] * sw[n][k];
    out[(t0 + ts) * NT + n] = acc;
}

// ---------------------------------------------------------------------------
extern "C" void kernel_launch(void* const* d_in, const int* in_sizes, int n_in,
                              void* d_out, int out_size) {
    const int*   x    = (const int*)d_in[0];
    const float* emb  = (const float*)d_in[1];
    const float* w_ih = (const float*)d_in[2];
    const float* w_hh = (const float*)d_in[3];
    const float* b_ih = (const float*)d_in[4];
    const float* b_hh = (const float*)d_in[5];
    const float* w_fc = (const float*)d_in[6];
    const float* b_fc = (const float*)d_in[7];
    float* out = (float*)d_out;

    float* pre; cudaGetSymbolAddress((void**)&pre, g_pre);
    float* hs;  cudaGetSymbolAddress((void**)&hs,  g_hs);

    const int lstm_smem = (G4 * WS_STRIDE + HID + G4) * (int)sizeof(float);
    cudaFuncSetAttribute(lstm_kernel,
                         cudaFuncAttributeMaxDynamicSharedMemorySize, lstm_smem);

    tokenize_kernel<<<SEQ / 256, 256>>>(x);
    precompute_kernel<<<SEQ / 16, 256>>>(emb, w_ih, b_ih, b_hh, pre);
    lstm_kernel<<<1, 512, lstm_smem>>>(w_hh, pre, hs);
    fc_kernel<<<SEQ / 16, 256>>>(hs, w_fc, b_fc, out);
}